// round 1
// baseline (speedup 1.0000x reference)
#include <cuda_runtime.h>
#include <cuda_bf16.h>
#include <math.h>

// Problem constants (fixed shapes for this dataset)
#define NN  100000      // nodes
#define NE  3200000     // edges
#define DH  64          // hidden dim
#define DTXF 16
#define DTX  32
#define BB  16384       // batch rows
#define BN_EPS 1e-5f

// ---------------- scratch (device globals; no allocation allowed) -------------
__device__ float g_h  [NN * DH];   // node features (layer input/output)
__device__ float g_x  [NN * DH];   // h @ W
__device__ float g_agg[NN * DH];   // aggregation accumulator
__device__ float g_deg [NN];
__device__ float g_dinv[NN];

// ---------------- 1. gather embeddings + init deg=1 (self loop) ---------------
__global__ void k_gather(const int* __restrict__ ids, const float* __restrict__ emb)
{
    int i = blockIdx.x * blockDim.x + threadIdx.x;
    if (i >= NN * DH) return;
    int node = i >> 6;
    int c    = i & 63;
    g_h[i] = emb[(long)ids[node] * DH + c];
    if (c == 0) g_deg[node] = 1.0f;   // self-loop weight
}

// ---------------- 2. degree accumulation over edges ---------------------------
__global__ void k_deg(const int* __restrict__ dst, const float* __restrict__ ew)
{
    int e = blockIdx.x * blockDim.x + threadIdx.x;
    if (e >= NE) return;
    atomicAdd(&g_deg[dst[e]], ew[e]);
}

// ---------------- 3. dinv = rsqrt(deg) ----------------------------------------
__global__ void k_dinv()
{
    int i = blockIdx.x * blockDim.x + threadIdx.x;
    if (i >= NN) return;
    float d = g_deg[i];
    g_dinv[i] = (d > 0.0f) ? rsqrtf(fmaxf(d, 1e-12f)) : 0.0f;
}

// ---------------- 4. x = h @ W ; agg = x * dinv^2 (self-loop term) -------------
// warp computes 4 rows; each lane owns 2 output columns (2*lane, 2*lane+1)
__global__ void k_gemm_init(const float* __restrict__ W)
{
    __shared__ float Ws[DH * DH];
    for (int i = threadIdx.x; i < DH * DH; i += blockDim.x) Ws[i] = W[i];
    __syncthreads();

    const int lane   = threadIdx.x & 31;
    const int warp   = blockIdx.x * (blockDim.x >> 5) + (threadIdx.x >> 5);
    const int nwarps = gridDim.x * (blockDim.x >> 5);

    for (int r0 = warp * 4; r0 < NN; r0 += nwarps * 4) {
        float2 hr[4];
        #pragma unroll
        for (int i = 0; i < 4; i++) {
            int r = r0 + i;
            hr[i] = (r < NN) ? ((const float2*)g_h)[r * 32 + lane] : make_float2(0.f, 0.f);
        }
        float2 acc[4] = {{0,0},{0,0},{0,0},{0,0}};
        #pragma unroll
        for (int k = 0; k < DH; k++) {
            float2 wv = ((const float2*)Ws)[k * 32 + lane];
            int owner = k >> 1;
            #pragma unroll
            for (int i = 0; i < 4; i++) {
                float hk = __shfl_sync(0xffffffffu, (k & 1) ? hr[i].y : hr[i].x, owner);
                acc[i].x += hk * wv.x;
                acc[i].y += hk * wv.y;
            }
        }
        #pragma unroll
        for (int i = 0; i < 4; i++) {
            int r = r0 + i;
            if (r >= NN) break;
            ((float2*)g_x)[r * 32 + lane] = acc[i];
            float di = g_dinv[r];
            float s  = di * di;
            float2 a = make_float2(acc[i].x * s, acc[i].y * s);
            ((float2*)g_agg)[r * 32 + lane] = a;
        }
    }
}

// ---------------- 5. edge scatter: agg[d] += x[s] * (dinv[s]*w*dinv[d]) --------
// 16 threads per edge, one float4 chunk each; vector reduction (no-return atomic)
__global__ void k_scatter(const int* __restrict__ src, const int* __restrict__ dst,
                          const float* __restrict__ ew)
{
    unsigned gid = blockIdx.x * blockDim.x + threadIdx.x;
    if (gid >= (unsigned)NE * 16u) return;
    int e = gid >> 4;
    int c = gid & 15;
    int s = src[e];
    int d = dst[e];
    float norm = g_dinv[s] * ew[e] * g_dinv[d];
    float4 v = ((const float4*)g_x)[s * 16 + c];
    float4 r = make_float4(v.x * norm, v.y * norm, v.z * norm, v.w * norm);
    float4* p = ((float4*)g_agg) + (d * 16 + c);
    asm volatile("red.global.add.v4.f32 [%0], {%1, %2, %3, %4};"
                 :: "l"(p), "f"(r.x), "f"(r.y), "f"(r.z), "f"(r.w) : "memory");
}

// ---------------- 6. h = relu(agg + b) -----------------------------------------
__global__ void k_finalize(const float* __restrict__ b)
{
    int i = blockIdx.x * blockDim.x + threadIdx.x;
    if (i >= NN * DH) return;
    g_h[i] = fmaxf(g_agg[i] + b[i & 63], 0.0f);
}

// ---------------- 7. fused MLP head --------------------------------------------
// one warp per batch row: tx-proj, gather se/re, z@Wc1(bn,relu), @Wc2(bn,relu), @Wc3
__global__ void k_mlp(const int* __restrict__ tsl, const int* __restrict__ trl,
                      const int* __restrict__ ptr, const float* __restrict__ txf,
                      const float* __restrict__ Wtx, const float* __restrict__ btx,
                      const float* __restrict__ Wc1, const float* __restrict__ bc1,
                      const float* __restrict__ g1,  const float* __restrict__ beta1,
                      const float* __restrict__ Wc2, const float* __restrict__ bc2,
                      const float* __restrict__ g2,  const float* __restrict__ beta2,
                      const float* __restrict__ Wc3, const float* __restrict__ bc3,
                      float* __restrict__ out)
{
    __shared__ float Wc1s[160 * 64];   // 40 KB
    for (int i = threadIdx.x; i < 160 * 64; i += blockDim.x) Wc1s[i] = Wc1[i];
    __syncthreads();

    const int lane = threadIdx.x & 31;
    const int row  = blockIdx.x * (blockDim.x >> 5) + (threadIdx.x >> 5);
    if (row >= BB) return;

    const float invs = rsqrtf(1.0f + BN_EPS);
    const unsigned FULL = 0xffffffffu;

    int off  = ptr[row];
    int sidx = tsl[row] + off;
    int ridx = trl[row] + off;

    // tx = relu(txf @ Wtx + btx) ; lane holds tx[lane]
    float f = (lane < DTXF) ? txf[row * DTXF + lane] : 0.0f;
    float acct = __ldg(&btx[lane]);
    #pragma unroll
    for (int k = 0; k < DTXF; k++) {
        float tk = __shfl_sync(FULL, f, k);
        acct += tk * __ldg(&Wtx[k * DTX + lane]);
    }
    float txv = fmaxf(acct, 0.0f);

    // z registers: z[j*32 + lane]
    float zr[5];
    zr[0] = g_h[sidx * DH + lane];
    zr[1] = g_h[sidx * DH + 32 + lane];
    zr[2] = g_h[ridx * DH + lane];
    zr[3] = g_h[ridx * DH + 32 + lane];
    zr[4] = txv;

    // z1 = relu(bn(z @ Wc1 + bc1)) ; lane owns cols 2*lane, 2*lane+1
    float2 a = make_float2(0.f, 0.f);
    #pragma unroll
    for (int k = 0; k < 160; k++) {
        float zk = __shfl_sync(FULL, zr[k >> 5], k & 31);
        float2 w = *(const float2*)&Wc1s[k * 64 + 2 * lane];
        a.x += zk * w.x;
        a.y += zk * w.y;
    }
    int c0 = 2 * lane, c1 = 2 * lane + 1;
    float z1x = fmaxf((a.x + __ldg(&bc1[c0])) * (__ldg(&g1[c0]) * invs) + __ldg(&beta1[c0]), 0.0f);
    float z1y = fmaxf((a.y + __ldg(&bc1[c1])) * (__ldg(&g1[c1]) * invs) + __ldg(&beta1[c1]), 0.0f);

    // z2 = relu(bn(z1 @ Wc2 + bc2)) ; lane owns col lane
    float acc2 = 0.0f;
    #pragma unroll
    for (int k = 0; k < DH; k++) {
        float zk = __shfl_sync(FULL, (k & 1) ? z1y : z1x, k >> 1);
        acc2 += zk * __ldg(&Wc2[k * 32 + lane]);
    }
    float z2v = fmaxf((acc2 + __ldg(&bc2[lane])) * (__ldg(&g2[lane]) * invs) + __ldg(&beta2[lane]), 0.0f);

    // out = z2 @ Wc3 + bc3 (warp reduce)
    float p = z2v * __ldg(&Wc3[lane]);
    #pragma unroll
    for (int o = 16; o > 0; o >>= 1) p += __shfl_xor_sync(FULL, p, o);
    if (lane == 0) out[row] = p + __ldg(&bc3[0]);
}

// =============================== launch ========================================
extern "C" void kernel_launch(void* const* d_in, const int* in_sizes, int n_in,
                              void* d_out, int out_size)
{
    const int*   ids  = (const int*)  d_in[0];   // x_node_global_ids (N,)
    const int*   ei   = (const int*)  d_in[1];   // edge_index (2,E)
    const float* ew   = (const float*)d_in[2];   // edge_weight (E,)
    const int*   tsl  = (const int*)  d_in[3];   // target_sender_local_idx (B,)
    const int*   trl  = (const int*)  d_in[4];   // target_receiver_local_idx (B,)
    const int*   ptr  = (const int*)  d_in[5];   // ptr (B+1,)
    const float* txf  = (const float*)d_in[6];   // target_tx_features (B,16)
    const float* emb  = (const float*)d_in[7];   // emb (V,64)
    const float* W0   = (const float*)d_in[8];
    const float* b0   = (const float*)d_in[9];
    const float* W1   = (const float*)d_in[10];
    const float* b1   = (const float*)d_in[11];
    const float* Wtx  = (const float*)d_in[12];
    const float* btx  = (const float*)d_in[13];
    const float* Wc1  = (const float*)d_in[14];
    const float* bc1  = (const float*)d_in[15];
    const float* g1   = (const float*)d_in[16];
    const float* beta1= (const float*)d_in[17];
    const float* Wc2  = (const float*)d_in[18];
    const float* bc2  = (const float*)d_in[19];
    const float* g2   = (const float*)d_in[20];
    const float* beta2= (const float*)d_in[21];
    const float* Wc3  = (const float*)d_in[22];
    const float* bc3  = (const float*)d_in[23];
    float* out = (float*)d_out;

    const int* src = ei;
    const int* dst = ei + NE;

    // gather + deg init
    k_gather<<<(NN * DH + 255) / 256, 256>>>(ids, emb);
    // degree
    k_deg<<<(NE + 255) / 256, 256>>>(dst, ew);
    k_dinv<<<(NN + 255) / 256, 256>>>();

    // GCN layer 0
    k_gemm_init<<<2048, 256>>>(W0);
    k_scatter<<<((unsigned)NE * 16u + 255u) / 256u, 256>>>(src, dst, ew);
    k_finalize<<<(NN * DH + 255) / 256, 256>>>(b0);

    // GCN layer 1
    k_gemm_init<<<2048, 256>>>(W1);
    k_scatter<<<((unsigned)NE * 16u + 255u) / 256u, 256>>>(src, dst, ew);
    k_finalize<<<(NN * DH + 255) / 256, 256>>>(b1);

    // fused MLP head (8 warps = 8 rows per block)
    k_mlp<<<BB / 8, 256>>>(tsl, trl, ptr, txf,
                           Wtx, btx, Wc1, bc1, g1, beta1,
                           Wc2, bc2, g2, beta2, Wc3, bc3, out);
}

// round 2
// speedup vs baseline: 1.6342x; 1.6342x over previous
#include <cuda_runtime.h>
#include <cuda_bf16.h>
#include <math.h>

#define NN  100000      // nodes
#define NE  3200000     // edges
#define DH  64
#define DTXF 16
#define DTX  32
#define BB  16384
#define BN_EPS 1e-5f

#define SCAN_BLK 1024
#define NSCAN ((NN + SCAN_BLK - 1) / SCAN_BLK)   // 98

// ---------------- scratch (device globals) ------------------------------------
__device__ float g_h   [NN * DH];
__device__ float g_x   [NN * DH];
__device__ float g_degw[NN];
__device__ float g_dinv[NN];
__device__ int   g_cnt [NN];
__device__ int   g_rs  [NN + 1];    // CSR row starts (by dst)
__device__ int   g_cur [NN];        // fill cursors
__device__ int   g_bsum[NSCAN];
__device__ int   g_boff[NSCAN];
__device__ int   g_csrc [NE];       // CSR: source node per slot
__device__ float g_cnorm[NE];       // CSR: precomputed norm per slot

// ---------------- 1. gather embeddings ----------------------------------------
__global__ void k_gather(const int* __restrict__ ids, const float* __restrict__ emb)
{
    int i = blockIdx.x * blockDim.x + threadIdx.x;
    if (i >= NN * DH) return;
    int node = i >> 6;
    int c    = i & 63;
    g_h[i] = emb[(long)ids[node] * DH + c];
}

// ---------------- 2. init counters --------------------------------------------
__global__ void k_init()
{
    int i = blockIdx.x * blockDim.x + threadIdx.x;
    if (i >= NN) return;
    g_cnt[i]  = 0;
    g_degw[i] = 1.0f;   // self-loop weight
}

// ---------------- 3. count in-degree + weighted degree -------------------------
__global__ void k_count(const int* __restrict__ dst, const float* __restrict__ ew)
{
    int e = blockIdx.x * blockDim.x + threadIdx.x;
    if (e >= NE) return;
    int d = dst[e];
    atomicAdd(&g_cnt[d], 1);
    atomicAdd(&g_degw[d], ew[e]);
}

// ---------------- 4. dinv -------------------------------------------------------
__global__ void k_dinv()
{
    int i = blockIdx.x * blockDim.x + threadIdx.x;
    if (i >= NN) return;
    float d = g_degw[i];
    g_dinv[i] = (d > 0.0f) ? rsqrtf(fmaxf(d, 1e-12f)) : 0.0f;
}

// ---------------- 5. scan (3 kernels) ------------------------------------------
__global__ void k_scan1()
{
    __shared__ int s[SCAN_BLK];
    int tid = threadIdx.x;
    int i = blockIdx.x * SCAN_BLK + tid;
    int v = (i < NN) ? g_cnt[i] : 0;
    s[tid] = v;
    __syncthreads();
    #pragma unroll
    for (int off = 1; off < SCAN_BLK; off <<= 1) {
        int t = (tid >= off) ? s[tid - off] : 0;
        __syncthreads();
        s[tid] += t;
        __syncthreads();
    }
    if (i < NN) g_rs[i] = s[tid] - v;           // exclusive within block
    if (tid == SCAN_BLK - 1) g_bsum[blockIdx.x] = s[tid];
}

__global__ void k_scan2()
{
    __shared__ int s[128];
    int tid = threadIdx.x;
    int v = (tid < NSCAN) ? g_bsum[tid] : 0;
    s[tid] = v;
    __syncthreads();
    #pragma unroll
    for (int off = 1; off < 128; off <<= 1) {
        int t = (tid >= off) ? s[tid - off] : 0;
        __syncthreads();
        s[tid] += t;
        __syncthreads();
    }
    if (tid < NSCAN) g_boff[tid] = s[tid] - v;  // exclusive
    if (tid == 127) g_rs[NN] = s[127];          // = NE
}

__global__ void k_scan3()
{
    int i = blockIdx.x * blockDim.x + threadIdx.x;
    if (i >= NN) return;
    int r = g_rs[i] + g_boff[i / SCAN_BLK];
    g_rs[i]  = r;
    g_cur[i] = r;
}

// ---------------- 6. fill CSR with precomputed norms ---------------------------
__global__ void k_fill(const int* __restrict__ src, const int* __restrict__ dst,
                       const float* __restrict__ ew)
{
    int e = blockIdx.x * blockDim.x + threadIdx.x;
    if (e >= NE) return;
    int s = src[e], d = dst[e];
    float norm = g_dinv[s] * ew[e] * g_dinv[d];
    int pos = atomicAdd(&g_cur[d], 1);
    g_csrc[pos]  = s;
    g_cnorm[pos] = norm;
}

// ---------------- 7. tiled GEMM: g_x = g_h @ W ----------------------------------
// 128 threads/block, 64 rows/block; thread = (ty 0..7) x (tx 0..15); 8 rows x 4 cols
__global__ void k_gemm(const float* __restrict__ W)
{
    __shared__ float hs[64][65];
    __shared__ float ws[64][64];
    int tid = threadIdx.x;
    int r0 = blockIdx.x * 64;

    for (int i = tid; i < 64 * 16; i += 128) {
        int r = i >> 4, c4 = (i & 15) * 4;
        float4 v = make_float4(0.f, 0.f, 0.f, 0.f);
        if (r0 + r < NN) v = ((const float4*)g_h)[(r0 + r) * 16 + (i & 15)];
        hs[r][c4] = v.x; hs[r][c4+1] = v.y; hs[r][c4+2] = v.z; hs[r][c4+3] = v.w;
        *((float4*)&ws[r][c4]) = ((const float4*)W)[i];
    }
    __syncthreads();

    int tx = tid & 15, ty = tid >> 4;
    int c0 = tx * 4;
    float4 acc[8];
    #pragma unroll
    for (int r = 0; r < 8; r++) acc[r] = make_float4(0.f, 0.f, 0.f, 0.f);

    #pragma unroll
    for (int k = 0; k < 64; k++) {
        float4 wv = *((const float4*)&ws[k][c0]);
        #pragma unroll
        for (int r = 0; r < 8; r++) {
            float a = hs[ty * 8 + r][k];
            acc[r].x += a * wv.x;
            acc[r].y += a * wv.y;
            acc[r].z += a * wv.z;
            acc[r].w += a * wv.w;
        }
    }
    #pragma unroll
    for (int r = 0; r < 8; r++) {
        int row = r0 + ty * 8 + r;
        if (row < NN) ((float4*)g_x)[row * 16 + tx] = acc[r];
    }
}

// ---------------- 8. gather aggregation + self-loop + bias + relu ---------------
// one warp per destination node; lane owns 2 columns (float2)
__global__ void k_agg(const float* __restrict__ b)
{
    int warp = blockIdx.x * (blockDim.x >> 5) + (threadIdx.x >> 5);
    if (warp >= NN) return;
    int lane = threadIdx.x & 31;

    int start = g_rs[warp];
    int end   = g_rs[warp + 1];
    float di  = g_dinv[warp];
    float sl  = di * di;

    float2 x2  = ((const float2*)g_x)[warp * 32 + lane];
    float2 acc = make_float2(x2.x * sl, x2.y * sl);

    int j = start;
    for (; j + 2 <= end; j += 2) {
        int   s0 = __ldg(&g_csrc[j]);
        int   s1 = __ldg(&g_csrc[j + 1]);
        float n0 = __ldg(&g_cnorm[j]);
        float n1 = __ldg(&g_cnorm[j + 1]);
        float2 v0 = ((const float2*)g_x)[s0 * 32 + lane];
        float2 v1 = ((const float2*)g_x)[s1 * 32 + lane];
        acc.x += n0 * v0.x + n1 * v1.x;
        acc.y += n0 * v0.y + n1 * v1.y;
    }
    if (j < end) {
        int   s0 = __ldg(&g_csrc[j]);
        float n0 = __ldg(&g_cnorm[j]);
        float2 v0 = ((const float2*)g_x)[s0 * 32 + lane];
        acc.x += n0 * v0.x;
        acc.y += n0 * v0.y;
    }

    float2 bb = ((const float2*)b)[lane];
    float2 o  = make_float2(fmaxf(acc.x + bb.x, 0.0f), fmaxf(acc.y + bb.y, 0.0f));
    ((float2*)g_h)[warp * 32 + lane] = o;
}

// ---------------- 9. fused MLP head ---------------------------------------------
__global__ void k_mlp(const int* __restrict__ tsl, const int* __restrict__ trl,
                      const int* __restrict__ ptr, const float* __restrict__ txf,
                      const float* __restrict__ Wtx, const float* __restrict__ btx,
                      const float* __restrict__ Wc1, const float* __restrict__ bc1,
                      const float* __restrict__ g1,  const float* __restrict__ beta1,
                      const float* __restrict__ Wc2, const float* __restrict__ bc2,
                      const float* __restrict__ g2,  const float* __restrict__ beta2,
                      const float* __restrict__ Wc3, const float* __restrict__ bc3,
                      float* __restrict__ out)
{
    __shared__ float Wc1s[160 * 64];
    for (int i = threadIdx.x; i < 160 * 64; i += blockDim.x) Wc1s[i] = Wc1[i];
    __syncthreads();

    const int lane = threadIdx.x & 31;
    const int row  = blockIdx.x * (blockDim.x >> 5) + (threadIdx.x >> 5);
    if (row >= BB) return;

    const float invs = rsqrtf(1.0f + BN_EPS);
    const unsigned FULL = 0xffffffffu;

    int off  = ptr[row];
    int sidx = tsl[row] + off;
    int ridx = trl[row] + off;

    float f = (lane < DTXF) ? txf[row * DTXF + lane] : 0.0f;
    float acct = __ldg(&btx[lane]);
    #pragma unroll
    for (int k = 0; k < DTXF; k++) {
        float tk = __shfl_sync(FULL, f, k);
        acct += tk * __ldg(&Wtx[k * DTX + lane]);
    }
    float txv = fmaxf(acct, 0.0f);

    float zr[5];
    zr[0] = g_h[sidx * DH + lane];
    zr[1] = g_h[sidx * DH + 32 + lane];
    zr[2] = g_h[ridx * DH + lane];
    zr[3] = g_h[ridx * DH + 32 + lane];
    zr[4] = txv;

    float2 a = make_float2(0.f, 0.f);
    #pragma unroll
    for (int k = 0; k < 160; k++) {
        float zk = __shfl_sync(FULL, zr[k >> 5], k & 31);
        float2 w = *(const float2*)&Wc1s[k * 64 + 2 * lane];
        a.x += zk * w.x;
        a.y += zk * w.y;
    }
    int c0 = 2 * lane, c1 = 2 * lane + 1;
    float z1x = fmaxf((a.x + __ldg(&bc1[c0])) * (__ldg(&g1[c0]) * invs) + __ldg(&beta1[c0]), 0.0f);
    float z1y = fmaxf((a.y + __ldg(&bc1[c1])) * (__ldg(&g1[c1]) * invs) + __ldg(&beta1[c1]), 0.0f);

    float acc2 = 0.0f;
    #pragma unroll
    for (int k = 0; k < DH; k++) {
        float zk = __shfl_sync(FULL, (k & 1) ? z1y : z1x, k >> 1);
        acc2 += zk * __ldg(&Wc2[k * 32 + lane]);
    }
    float z2v = fmaxf((acc2 + __ldg(&bc2[lane])) * (__ldg(&g2[lane]) * invs) + __ldg(&beta2[lane]), 0.0f);

    float p = z2v * __ldg(&Wc3[lane]);
    #pragma unroll
    for (int o = 16; o > 0; o >>= 1) p += __shfl_xor_sync(FULL, p, o);
    if (lane == 0) out[row] = p + __ldg(&bc3[0]);
}

// =============================== launch ========================================
extern "C" void kernel_launch(void* const* d_in, const int* in_sizes, int n_in,
                              void* d_out, int out_size)
{
    const int*   ids  = (const int*)  d_in[0];
    const int*   ei   = (const int*)  d_in[1];
    const float* ew   = (const float*)d_in[2];
    const int*   tsl  = (const int*)  d_in[3];
    const int*   trl  = (const int*)  d_in[4];
    const int*   ptr  = (const int*)  d_in[5];
    const float* txf  = (const float*)d_in[6];
    const float* emb  = (const float*)d_in[7];
    const float* W0   = (const float*)d_in[8];
    const float* b0   = (const float*)d_in[9];
    const float* W1   = (const float*)d_in[10];
    const float* b1   = (const float*)d_in[11];
    const float* Wtx  = (const float*)d_in[12];
    const float* btx  = (const float*)d_in[13];
    const float* Wc1  = (const float*)d_in[14];
    const float* bc1  = (const float*)d_in[15];
    const float* g1   = (const float*)d_in[16];
    const float* beta1= (const float*)d_in[17];
    const float* Wc2  = (const float*)d_in[18];
    const float* bc2  = (const float*)d_in[19];
    const float* g2   = (const float*)d_in[20];
    const float* beta2= (const float*)d_in[21];
    const float* Wc3  = (const float*)d_in[22];
    const float* bc3  = (const float*)d_in[23];
    float* out = (float*)d_out;

    const int* src = ei;
    const int* dst = ei + NE;

    // embedding gather (independent of CSR build)
    k_gather<<<(NN * DH + 255) / 256, 256>>>(ids, emb);

    // CSR build
    k_init <<<(NN + 255) / 256, 256>>>();
    k_count<<<(NE + 255) / 256, 256>>>(dst, ew);
    k_dinv <<<(NN + 255) / 256, 256>>>();
    k_scan1<<<NSCAN, SCAN_BLK>>>();
    k_scan2<<<1, 128>>>();
    k_scan3<<<(NN + 255) / 256, 256>>>();
    k_fill <<<(NE + 255) / 256, 256>>>(src, dst, ew);

    // GCN layer 0
    k_gemm<<<(NN + 63) / 64, 128>>>(W0);
    k_agg <<<(NN + 7) / 8, 256>>>(b0);

    // GCN layer 1
    k_gemm<<<(NN + 63) / 64, 128>>>(W1);
    k_agg <<<(NN + 7) / 8, 256>>>(b1);

    // fused MLP head
    k_mlp<<<BB / 8, 256>>>(tsl, trl, ptr, txf,
                           Wtx, btx, Wc1, bc1, g1, beta1,
                           Wc2, bc2, g2, beta2, Wc3, bc3, out);
}

// round 3
// speedup vs baseline: 1.6754x; 1.0252x over previous
#include <cuda_runtime.h>
#include <cuda_fp16.h>
#include <math.h>

#define NN  100000      // nodes
#define NE  3200000     // edges
#define DH  64
#define DTXF 16
#define DTX  32
#define BB  16384
#define BN_EPS 1e-5f

#define SCAN_BLK 1024
#define NSCAN ((NN + SCAN_BLK - 1) / SCAN_BLK)   // 98

// ---------------- scratch (device globals) ------------------------------------
__device__ float   g_h   [NN * DH];
__device__ float   g_x   [NN * DH];    // fp32 x (self-loop term, exact)
__device__ __half2 g_xh  [NN * 32];    // fp16 copy of x (neighbor reads)
__device__ float   g_degw[NN];
__device__ float   g_dinv[NN];
__device__ int     g_cnt [NN];
__device__ int     g_rs  [NN + 1];     // CSR row starts (by dst)
__device__ int     g_cur [NN];         // fill cursors
__device__ int     g_bsum[NSCAN];
__device__ int     g_boff[NSCAN];
__device__ int2    g_cedge[NE];        // CSR: {src, norm-bits} per slot

// ---------------- 1. gather embeddings + init counters -------------------------
__global__ void k_gather(const int* __restrict__ ids, const float* __restrict__ emb)
{
    int i = blockIdx.x * blockDim.x + threadIdx.x;
    if (i >= NN * DH) return;
    int node = i >> 6;
    int c    = i & 63;
    g_h[i] = emb[(long)ids[node] * DH + c];
    if (c == 0) { g_cnt[node] = 0; g_degw[node] = 1.0f; }  // self-loop weight
}

// ---------------- 2. count in-degree + weighted degree --------------------------
__global__ void k_count(const int* __restrict__ dst, const float* __restrict__ ew)
{
    int e = blockIdx.x * blockDim.x + threadIdx.x;
    if (e >= NE) return;
    int d = dst[e];
    atomicAdd(&g_cnt[d], 1);
    atomicAdd(&g_degw[d], ew[e]);
}

// ---------------- 3. scan (3 kernels; dinv fused into scan3) --------------------
__global__ void k_scan1()
{
    __shared__ int s[SCAN_BLK];
    int tid = threadIdx.x;
    int i = blockIdx.x * SCAN_BLK + tid;
    int v = (i < NN) ? g_cnt[i] : 0;
    s[tid] = v;
    __syncthreads();
    #pragma unroll
    for (int off = 1; off < SCAN_BLK; off <<= 1) {
        int t = (tid >= off) ? s[tid - off] : 0;
        __syncthreads();
        s[tid] += t;
        __syncthreads();
    }
    if (i < NN) g_rs[i] = s[tid] - v;           // exclusive within block
    if (tid == SCAN_BLK - 1) g_bsum[blockIdx.x] = s[tid];
}

__global__ void k_scan2()
{
    __shared__ int s[128];
    int tid = threadIdx.x;
    int v = (tid < NSCAN) ? g_bsum[tid] : 0;
    s[tid] = v;
    __syncthreads();
    #pragma unroll
    for (int off = 1; off < 128; off <<= 1) {
        int t = (tid >= off) ? s[tid - off] : 0;
        __syncthreads();
        s[tid] += t;
        __syncthreads();
    }
    if (tid < NSCAN) g_boff[tid] = s[tid] - v;  // exclusive
    if (tid == 127) g_rs[NN] = s[127];          // = NE
}

__global__ void k_scan3()
{
    int i = blockIdx.x * blockDim.x + threadIdx.x;
    if (i >= NN) return;
    int r = g_rs[i] + g_boff[i / SCAN_BLK];
    g_rs[i]  = r;
    g_cur[i] = r;
    float d = g_degw[i];
    g_dinv[i] = (d > 0.0f) ? rsqrtf(fmaxf(d, 1e-12f)) : 0.0f;
}

// ---------------- 4. fill CSR with precomputed norms ----------------------------
__global__ void k_fill(const int* __restrict__ src, const int* __restrict__ dst,
                       const float* __restrict__ ew)
{
    int e = blockIdx.x * blockDim.x + threadIdx.x;
    if (e >= NE) return;
    int s = src[e], d = dst[e];
    float norm = g_dinv[s] * ew[e] * g_dinv[d];
    int pos = atomicAdd(&g_cur[d], 1);
    g_cedge[pos] = make_int2(s, __float_as_int(norm));
}

// ---------------- 5. tiled GEMM: g_x = g_h @ W (+ fp16 copy) --------------------
__global__ void k_gemm(const float* __restrict__ W)
{
    __shared__ float hs[64][65];
    __shared__ float ws[64][64];
    int tid = threadIdx.x;
    int r0 = blockIdx.x * 64;

    for (int i = tid; i < 64 * 16; i += 128) {
        int r = i >> 4, c4 = (i & 15) * 4;
        float4 v = make_float4(0.f, 0.f, 0.f, 0.f);
        if (r0 + r < NN) v = ((const float4*)g_h)[(r0 + r) * 16 + (i & 15)];
        hs[r][c4] = v.x; hs[r][c4+1] = v.y; hs[r][c4+2] = v.z; hs[r][c4+3] = v.w;
        *((float4*)&ws[r][c4]) = ((const float4*)W)[i];
    }
    __syncthreads();

    int tx = tid & 15, ty = tid >> 4;
    int c0 = tx * 4;
    float4 acc[8];
    #pragma unroll
    for (int r = 0; r < 8; r++) acc[r] = make_float4(0.f, 0.f, 0.f, 0.f);

    #pragma unroll
    for (int k = 0; k < 64; k++) {
        float4 wv = *((const float4*)&ws[k][c0]);
        #pragma unroll
        for (int r = 0; r < 8; r++) {
            float a = hs[ty * 8 + r][k];
            acc[r].x += a * wv.x;
            acc[r].y += a * wv.y;
            acc[r].z += a * wv.z;
            acc[r].w += a * wv.w;
        }
    }
    #pragma unroll
    for (int r = 0; r < 8; r++) {
        int row = r0 + ty * 8 + r;
        if (row < NN) {
            ((float4*)g_x)[row * 16 + tx] = acc[r];
            g_xh[row * 32 + tx * 2]     = __floats2half2_rn(acc[r].x, acc[r].y);
            g_xh[row * 32 + tx * 2 + 1] = __floats2half2_rn(acc[r].z, acc[r].w);
        }
    }
}

// ---------------- 6. gather aggregation + self-loop + bias + relu ----------------
// one warp per destination node; lane owns 2 columns; neighbors read fp16
__global__ void k_agg(const float* __restrict__ b)
{
    int warp = blockIdx.x * (blockDim.x >> 5) + (threadIdx.x >> 5);
    if (warp >= NN) return;
    int lane = threadIdx.x & 31;

    int start = g_rs[warp];
    int end   = g_rs[warp + 1];
    float di  = g_dinv[warp];
    float sl  = di * di;

    float2 x2  = ((const float2*)g_x)[warp * 32 + lane];
    float2 acc = make_float2(x2.x * sl, x2.y * sl);

    int j = start;
    for (; j + 4 <= end; j += 4) {
        int2 e0 = __ldg(&g_cedge[j]);
        int2 e1 = __ldg(&g_cedge[j + 1]);
        int2 e2 = __ldg(&g_cedge[j + 2]);
        int2 e3 = __ldg(&g_cedge[j + 3]);
        float2 v0 = __half22float2(__ldg(&g_xh[e0.x * 32 + lane]));
        float2 v1 = __half22float2(__ldg(&g_xh[e1.x * 32 + lane]));
        float2 v2 = __half22float2(__ldg(&g_xh[e2.x * 32 + lane]));
        float2 v3 = __half22float2(__ldg(&g_xh[e3.x * 32 + lane]));
        float n0 = __int_as_float(e0.y), n1 = __int_as_float(e1.y);
        float n2 = __int_as_float(e2.y), n3 = __int_as_float(e3.y);
        acc.x += n0 * v0.x + n1 * v1.x + n2 * v2.x + n3 * v3.x;
        acc.y += n0 * v0.y + n1 * v1.y + n2 * v2.y + n3 * v3.y;
    }
    for (; j < end; j++) {
        int2 e0 = __ldg(&g_cedge[j]);
        float2 v0 = __half22float2(__ldg(&g_xh[e0.x * 32 + lane]));
        float n0 = __int_as_float(e0.y);
        acc.x += n0 * v0.x;
        acc.y += n0 * v0.y;
    }

    float2 bb = ((const float2*)b)[lane];
    float2 o  = make_float2(fmaxf(acc.x + bb.x, 0.0f), fmaxf(acc.y + bb.y, 0.0f));
    ((float2*)g_h)[warp * 32 + lane] = o;
}

// ---------------- 7. fused MLP head ----------------------------------------------
__global__ void k_mlp(const int* __restrict__ tsl, const int* __restrict__ trl,
                      const int* __restrict__ ptr, const float* __restrict__ txf,
                      const float* __restrict__ Wtx, const float* __restrict__ btx,
                      const float* __restrict__ Wc1, const float* __restrict__ bc1,
                      const float* __restrict__ g1,  const float* __restrict__ beta1,
                      const float* __restrict__ Wc2, const float* __restrict__ bc2,
                      const float* __restrict__ g2,  const float* __restrict__ beta2,
                      const float* __restrict__ Wc3, const float* __restrict__ bc3,
                      float* __restrict__ out)
{
    __shared__ float Wc1s[160 * 64];
    for (int i = threadIdx.x; i < 160 * 64; i += blockDim.x) Wc1s[i] = Wc1[i];
    __syncthreads();

    const int lane = threadIdx.x & 31;
    const int row  = blockIdx.x * (blockDim.x >> 5) + (threadIdx.x >> 5);
    if (row >= BB) return;

    const float invs = rsqrtf(1.0f + BN_EPS);
    const unsigned FULL = 0xffffffffu;

    int off  = ptr[row];
    int sidx = tsl[row] + off;
    int ridx = trl[row] + off;

    float f = (lane < DTXF) ? txf[row * DTXF + lane] : 0.0f;
    float acct = __ldg(&btx[lane]);
    #pragma unroll
    for (int k = 0; k < DTXF; k++) {
        float tk = __shfl_sync(FULL, f, k);
        acct += tk * __ldg(&Wtx[k * DTX + lane]);
    }
    float txv = fmaxf(acct, 0.0f);

    float zr[5];
    zr[0] = g_h[sidx * DH + lane];
    zr[1] = g_h[sidx * DH + 32 + lane];
    zr[2] = g_h[ridx * DH + lane];
    zr[3] = g_h[ridx * DH + 32 + lane];
    zr[4] = txv;

    float2 a = make_float2(0.f, 0.f);
    #pragma unroll
    for (int k = 0; k < 160; k++) {
        float zk = __shfl_sync(FULL, zr[k >> 5], k & 31);
        float2 w = *(const float2*)&Wc1s[k * 64 + 2 * lane];
        a.x += zk * w.x;
        a.y += zk * w.y;
    }
    int c0 = 2 * lane, c1 = 2 * lane + 1;
    float z1x = fmaxf((a.x + __ldg(&bc1[c0])) * (__ldg(&g1[c0]) * invs) + __ldg(&beta1[c0]), 0.0f);
    float z1y = fmaxf((a.y + __ldg(&bc1[c1])) * (__ldg(&g1[c1]) * invs) + __ldg(&beta1[c1]), 0.0f);

    float acc2 = 0.0f;
    #pragma unroll
    for (int k = 0; k < DH; k++) {
        float zk = __shfl_sync(FULL, (k & 1) ? z1y : z1x, k >> 1);
        acc2 += zk * __ldg(&Wc2[k * 32 + lane]);
    }
    float z2v = fmaxf((acc2 + __ldg(&bc2[lane])) * (__ldg(&g2[lane]) * invs) + __ldg(&beta2[lane]), 0.0f);

    float p = z2v * __ldg(&Wc3[lane]);
    #pragma unroll
    for (int o = 16; o > 0; o >>= 1) p += __shfl_xor_sync(FULL, p, o);
    if (lane == 0) out[row] = p + __ldg(&bc3[0]);
}

// =============================== launch ========================================
extern "C" void kernel_launch(void* const* d_in, const int* in_sizes, int n_in,
                              void* d_out, int out_size)
{
    const int*   ids  = (const int*)  d_in[0];
    const int*   ei   = (const int*)  d_in[1];
    const float* ew   = (const float*)d_in[2];
    const int*   tsl  = (const int*)  d_in[3];
    const int*   trl  = (const int*)  d_in[4];
    const int*   ptr  = (const int*)  d_in[5];
    const float* txf  = (const float*)d_in[6];
    const float* emb  = (const float*)d_in[7];
    const float* W0   = (const float*)d_in[8];
    const float* b0   = (const float*)d_in[9];
    const float* W1   = (const float*)d_in[10];
    const float* b1   = (const float*)d_in[11];
    const float* Wtx  = (const float*)d_in[12];
    const float* btx  = (const float*)d_in[13];
    const float* Wc1  = (const float*)d_in[14];
    const float* bc1  = (const float*)d_in[15];
    const float* g1   = (const float*)d_in[16];
    const float* beta1= (const float*)d_in[17];
    const float* Wc2  = (const float*)d_in[18];
    const float* bc2  = (const float*)d_in[19];
    const float* g2   = (const float*)d_in[20];
    const float* beta2= (const float*)d_in[21];
    const float* Wc3  = (const float*)d_in[22];
    const float* bc3  = (const float*)d_in[23];
    float* out = (float*)d_out;

    const int* src = ei;
    const int* dst = ei + NE;

    // embedding gather + counter init
    k_gather<<<(NN * DH + 255) / 256, 256>>>(ids, emb);

    // CSR build
    k_count<<<(NE + 255) / 256, 256>>>(dst, ew);
    k_scan1<<<NSCAN, SCAN_BLK>>>();
    k_scan2<<<1, 128>>>();
    k_scan3<<<(NN + 255) / 256, 256>>>();
    k_fill <<<(NE + 255) / 256, 256>>>(src, dst, ew);

    // GCN layer 0
    k_gemm<<<(NN + 63) / 64, 128>>>(W0);
    k_agg <<<(NN + 7) / 8, 256>>>(b0);

    // GCN layer 1
    k_gemm<<<(NN + 63) / 64, 128>>>(W1);
    k_agg <<<(NN + 7) / 8, 256>>>(b1);

    // fused MLP head
    k_mlp<<<BB / 8, 256>>>(tsl, trl, ptr, txf,
                           Wtx, btx, Wc1, bc1, g1, beta1,
                           Wc2, bc2, g2, beta2, Wc3, bc3, out);
}

// round 4
// speedup vs baseline: 1.7682x; 1.0554x over previous
#include <cuda_runtime.h>
#include <cuda_fp16.h>
#include <math.h>

#define NN  100000      // nodes
#define NE  3200000     // edges
#define DH  64
#define DTXF 16
#define DTX  32
#define BB  16384
#define BN_EPS 1e-5f

#define SCAN_BLK 1024
#define NSCAN ((NN + SCAN_BLK - 1) / SCAN_BLK)   // 98

#define GEMMB ((NN + 63) / 64)                   // 1563 gemm blocks
#define FILLB 4096                               // fill blocks appended to layer-0 gemm

// ---------------- scratch (device globals) ------------------------------------
__device__ float   g_h   [NN * DH];
__device__ __half2 g_xh  [NN * 32];    // fp16 rows of (h@W) * dinv[row]
__device__ float   g_degw[NN];
__device__ float   g_dinv[NN];
__device__ int     g_cnt [NN];
__device__ int     g_rs  [NN + 1];     // CSR row starts (by dst)
__device__ int     g_cur [NN];         // fill cursors
__device__ int     g_bsum[NSCAN];
__device__ int2    g_cedge[NE];        // CSR: {src, weight-bits}

// ---------------- 1. gather embeddings + init counters -------------------------
__global__ void k_gather(const int* __restrict__ ids, const float* __restrict__ emb)
{
    int i = blockIdx.x * blockDim.x + threadIdx.x;
    if (i >= NN * DH) return;
    int node = i >> 6;
    int c    = i & 63;
    g_h[i] = emb[(long)ids[node] * DH + c];
    if (c == 0) { g_cnt[node] = 0; g_degw[node] = 1.0f; }  // self-loop weight
}

// ---------------- 2. count in-degree + weighted degree --------------------------
__global__ void k_count(const int* __restrict__ dst, const float* __restrict__ ew)
{
    int e = blockIdx.x * blockDim.x + threadIdx.x;
    if (e >= NE) return;
    int d = dst[e];
    atomicAdd(&g_cnt[d], 1);
    atomicAdd(&g_degw[d], ew[e]);
}

// ---------------- 3a. scan within 1024-blocks ----------------------------------
__global__ void k_scan1()
{
    __shared__ int s[SCAN_BLK];
    int tid = threadIdx.x;
    int i = blockIdx.x * SCAN_BLK + tid;
    int v = (i < NN) ? g_cnt[i] : 0;
    s[tid] = v;
    __syncthreads();
    #pragma unroll
    for (int off = 1; off < SCAN_BLK; off <<= 1) {
        int t = (tid >= off) ? s[tid - off] : 0;
        __syncthreads();
        s[tid] += t;
        __syncthreads();
    }
    if (i < NN) g_rs[i] = s[tid] - v;           // exclusive within block
    if (tid == SCAN_BLK - 1) g_bsum[blockIdx.x] = s[tid];
}

// ---------------- 3b. fused block-offset scan + finalize row starts + dinv ------
__global__ void k_scan23()
{
    __shared__ int bs[NSCAN];
    __shared__ int total_s;
    int tid = threadIdx.x;
    if (tid < NSCAN) bs[tid] = g_bsum[tid];
    __syncthreads();
    if (tid == 0) {
        int run = 0;
        for (int k = 0; k < NSCAN; k++) { int v = bs[k]; bs[k] = run; run += v; }
        total_s = run;
    }
    __syncthreads();
    int i = blockIdx.x * blockDim.x + tid;
    if (i == 0) g_rs[NN] = total_s;             // = NE
    if (i >= NN) return;
    int r = g_rs[i] + bs[i / SCAN_BLK];
    g_rs[i]  = r;
    g_cur[i] = r;
    float d = g_degw[i];
    g_dinv[i] = (d > 0.0f) ? rsqrtf(fmaxf(d, 1e-12f)) : 0.0f;
}

// ---------------- 4. fused GEMM (+ optional CSR fill blocks) --------------------
// blocks [0, GEMMB): xs = (g_h @ W) * dinv[row] -> g_xh (fp16)
// blocks [GEMMB, GEMMB+FILLB) when do_fill: CSR fill {src, w}
__global__ void k_gemmfill(const float* __restrict__ W,
                           const int* __restrict__ src, const int* __restrict__ dst,
                           const float* __restrict__ ew, int do_fill)
{
    __shared__ float hs[64][65];
    __shared__ float ws[64][64];
    int tid = threadIdx.x;

    if (blockIdx.x >= GEMMB) {
        // ---- CSR fill ----
        for (int e = (blockIdx.x - GEMMB) * blockDim.x + tid; e < NE;
             e += FILLB * blockDim.x) {
            int d = dst[e];
            int pos = atomicAdd(&g_cur[d], 1);
            g_cedge[pos] = make_int2(src[e], __float_as_int(ew[e]));
        }
        return;
    }

    // ---- GEMM tile ----
    int r0 = blockIdx.x * 64;
    for (int i = tid; i < 64 * 16; i += 128) {
        int r = i >> 4, c4 = (i & 15) * 4;
        float4 v = make_float4(0.f, 0.f, 0.f, 0.f);
        if (r0 + r < NN) v = ((const float4*)g_h)[(r0 + r) * 16 + (i & 15)];
        hs[r][c4] = v.x; hs[r][c4+1] = v.y; hs[r][c4+2] = v.z; hs[r][c4+3] = v.w;
        *((float4*)&ws[r][c4]) = ((const float4*)W)[i];
    }
    __syncthreads();

    int tx = tid & 15, ty = tid >> 4;
    int c0 = tx * 4;
    float4 acc[8];
    #pragma unroll
    for (int r = 0; r < 8; r++) acc[r] = make_float4(0.f, 0.f, 0.f, 0.f);

    #pragma unroll
    for (int k = 0; k < 64; k++) {
        float4 wv = *((const float4*)&ws[k][c0]);
        #pragma unroll
        for (int r = 0; r < 8; r++) {
            float a = hs[ty * 8 + r][k];
            acc[r].x += a * wv.x;
            acc[r].y += a * wv.y;
            acc[r].z += a * wv.z;
            acc[r].w += a * wv.w;
        }
    }
    #pragma unroll
    for (int r = 0; r < 8; r++) {
        int row = r0 + ty * 8 + r;
        if (row < NN) {
            float di = g_dinv[row];
            g_xh[row * 32 + tx * 2]     = __floats2half2_rn(acc[r].x * di, acc[r].y * di);
            g_xh[row * 32 + tx * 2 + 1] = __floats2half2_rn(acc[r].z * di, acc[r].w * di);
        }
    }
}

// ---------------- 5. gather aggregation + self-loop + bias + relu ----------------
// one warp per destination node; lane owns 2 columns; rows pre-scaled by dinv[src]
__global__ void k_agg(const float* __restrict__ b)
{
    int warp = blockIdx.x * (blockDim.x >> 5) + (threadIdx.x >> 5);
    if (warp >= NN) return;
    int lane = threadIdx.x & 31;

    int start = g_rs[warp];
    int end   = g_rs[warp + 1];
    float di  = g_dinv[warp];

    // self term: dinv^2 * x[d] = dinv * xs[d]
    float2 xs  = __half22float2(__ldg(&g_xh[warp * 32 + lane]));
    float2 acc = make_float2(xs.x * di, xs.y * di);

    int cnt = end - start;
    int n8  = start + (cnt & ~7);
    int j = start;
    for (; j < n8; j += 8) {
        int2 e[8];
        #pragma unroll
        for (int k = 0; k < 8; k++) e[k] = __ldg(&g_cedge[j + k]);
        float2 v[8];
        #pragma unroll
        for (int k = 0; k < 8; k++) v[k] = __half22float2(__ldg(&g_xh[e[k].x * 32 + lane]));
        #pragma unroll
        for (int k = 0; k < 8; k++) {
            float n = di * __int_as_float(e[k].y);
            acc.x += n * v[k].x;
            acc.y += n * v[k].y;
        }
    }
    for (; j < end; j++) {
        int2 e0 = __ldg(&g_cedge[j]);
        float2 v0 = __half22float2(__ldg(&g_xh[e0.x * 32 + lane]));
        float n = di * __int_as_float(e0.y);
        acc.x += n * v0.x;
        acc.y += n * v0.y;
    }

    float2 bb = ((const float2*)b)[lane];
    float2 o  = make_float2(fmaxf(acc.x + bb.x, 0.0f), fmaxf(acc.y + bb.y, 0.0f));
    ((float2*)g_h)[warp * 32 + lane] = o;
}

// ---------------- 6. fused MLP head ----------------------------------------------
__global__ void k_mlp(const int* __restrict__ tsl, const int* __restrict__ trl,
                      const int* __restrict__ ptr, const float* __restrict__ txf,
                      const float* __restrict__ Wtx, const float* __restrict__ btx,
                      const float* __restrict__ Wc1, const float* __restrict__ bc1,
                      const float* __restrict__ g1,  const float* __restrict__ beta1,
                      const float* __restrict__ Wc2, const float* __restrict__ bc2,
                      const float* __restrict__ g2,  const float* __restrict__ beta2,
                      const float* __restrict__ Wc3, const float* __restrict__ bc3,
                      float* __restrict__ out)
{
    __shared__ float Wc1s[160 * 64];
    for (int i = threadIdx.x; i < 160 * 64; i += blockDim.x) Wc1s[i] = Wc1[i];
    __syncthreads();

    const int lane = threadIdx.x & 31;
    const int row  = blockIdx.x * (blockDim.x >> 5) + (threadIdx.x >> 5);
    if (row >= BB) return;

    const float invs = rsqrtf(1.0f + BN_EPS);
    const unsigned FULL = 0xffffffffu;

    int off  = ptr[row];
    int sidx = tsl[row] + off;
    int ridx = trl[row] + off;

    float f = (lane < DTXF) ? txf[row * DTXF + lane] : 0.0f;
    float acct = __ldg(&btx[lane]);
    #pragma unroll
    for (int k = 0; k < DTXF; k++) {
        float tk = __shfl_sync(FULL, f, k);
        acct += tk * __ldg(&Wtx[k * DTX + lane]);
    }
    float txv = fmaxf(acct, 0.0f);

    float zr[5];
    zr[0] = g_h[sidx * DH + lane];
    zr[1] = g_h[sidx * DH + 32 + lane];
    zr[2] = g_h[ridx * DH + lane];
    zr[3] = g_h[ridx * DH + 32 + lane];
    zr[4] = txv;

    float2 a = make_float2(0.f, 0.f);
    #pragma unroll
    for (int k = 0; k < 160; k++) {
        float zk = __shfl_sync(FULL, zr[k >> 5], k & 31);
        float2 w = *(const float2*)&Wc1s[k * 64 + 2 * lane];
        a.x += zk * w.x;
        a.y += zk * w.y;
    }
    int c0 = 2 * lane, c1 = 2 * lane + 1;
    float z1x = fmaxf((a.x + __ldg(&bc1[c0])) * (__ldg(&g1[c0]) * invs) + __ldg(&beta1[c0]), 0.0f);
    float z1y = fmaxf((a.y + __ldg(&bc1[c1])) * (__ldg(&g1[c1]) * invs) + __ldg(&beta1[c1]), 0.0f);

    float acc2 = 0.0f;
    #pragma unroll
    for (int k = 0; k < DH; k++) {
        float zk = __shfl_sync(FULL, (k & 1) ? z1y : z1x, k >> 1);
        acc2 += zk * __ldg(&Wc2[k * 32 + lane]);
    }
    float z2v = fmaxf((acc2 + __ldg(&bc2[lane])) * (__ldg(&g2[lane]) * invs) + __ldg(&beta2[lane]), 0.0f);

    float p = z2v * __ldg(&Wc3[lane]);
    #pragma unroll
    for (int o = 16; o > 0; o >>= 1) p += __shfl_xor_sync(FULL, p, o);
    if (lane == 0) out[row] = p + __ldg(&bc3[0]);
}

// =============================== launch ========================================
extern "C" void kernel_launch(void* const* d_in, const int* in_sizes, int n_in,
                              void* d_out, int out_size)
{
    const int*   ids  = (const int*)  d_in[0];
    const int*   ei   = (const int*)  d_in[1];
    const float* ew   = (const float*)d_in[2];
    const int*   tsl  = (const int*)  d_in[3];
    const int*   trl  = (const int*)  d_in[4];
    const int*   ptr  = (const int*)  d_in[5];
    const float* txf  = (const float*)d_in[6];
    const float* emb  = (const float*)d_in[7];
    const float* W0   = (const float*)d_in[8];
    const float* b0   = (const float*)d_in[9];
    const float* W1   = (const float*)d_in[10];
    const float* b1   = (const float*)d_in[11];
    const float* Wtx  = (const float*)d_in[12];
    const float* btx  = (const float*)d_in[13];
    const float* Wc1  = (const float*)d_in[14];
    const float* bc1  = (const float*)d_in[15];
    const float* g1   = (const float*)d_in[16];
    const float* beta1= (const float*)d_in[17];
    const float* Wc2  = (const float*)d_in[18];
    const float* bc2  = (const float*)d_in[19];
    const float* g2   = (const float*)d_in[20];
    const float* beta2= (const float*)d_in[21];
    const float* Wc3  = (const float*)d_in[22];
    const float* bc3  = (const float*)d_in[23];
    float* out = (float*)d_out;

    const int* src = ei;
    const int* dst = ei + NE;

    // 1 embedding gather + counter init
    k_gather<<<(NN * DH + 255) / 256, 256>>>(ids, emb);
    // 2 degree/count
    k_count<<<(NE + 255) / 256, 256>>>(dst, ew);
    // 3-4 scan + dinv
    k_scan1 <<<NSCAN, SCAN_BLK>>>();
    k_scan23<<<(NN + 255) / 256, 256>>>();

    // 5 GCN layer 0 GEMM + CSR fill (overlapped)
    k_gemmfill<<<GEMMB + FILLB, 128>>>(W0, src, dst, ew, 1);
    // 6 layer 0 aggregation   (<- ncu -s 5 profiles this)
    k_agg<<<(NN + 7) / 8, 256>>>(b0);

    // 7-8 GCN layer 1
    k_gemmfill<<<GEMMB, 128>>>(W1, src, dst, ew, 0);
    k_agg<<<(NN + 7) / 8, 256>>>(b1);

    // 9 fused MLP head
    k_mlp<<<BB / 8, 256>>>(tsl, trl, ptr, txf,
                           Wtx, btx, Wc1, bc1, g1, beta1,
                           Wc2, bc2, g2, beta2, Wc3, bc3, out);
}

// round 6
// speedup vs baseline: 1.8719x; 1.0586x over previous
#include <cuda_runtime.h>
#include <cuda_fp16.h>
#include <math.h>

#define NN  100000      // nodes
#define NE  3200000     // edges
#define DH  64
#define DTXF 16
#define DTX  32
#define BB  16384
#define BN_EPS 1e-5f

#define SCAN_BLK 1024
#define NSCAN ((NN + SCAN_BLK - 1) / SCAN_BLK)   // 98

#define GATHB ((NN * DH + 255) / 256)            // gather blocks
#define CNTB  2048                               // count blocks (grid-stride)
#define GEMMB ((NN + 63) / 64)                   // 1563 gemm blocks
#define FILLB 4096                               // fill blocks (layer 0)
#define FLAGB (BB / 128)                         // flag blocks (layer 1): 128*128 = BB

// ---------------- scratch (device globals; all self-resetting or overwritten) ---
__device__ float   g_h   [NN * DH];
__device__ __half2 g_xh  [NN * 32];    // fp16 rows of (h@W) * dinv[row]
__device__ float   g_degw[NN];         // starts 0 each call (reset in k_scan23)
__device__ float   g_dinv[NN];
__device__ int     g_cnt [NN];         // starts 0 each call (reset in k_scan1)
__device__ int     g_rs  [NN + 1];     // CSR row starts (by dst)
__device__ int     g_cur [NN];         // fill cursors
__device__ int     g_bsum[NSCAN];
__device__ int     g_need[NN];         // starts 0 each call (reset in sparse k_agg)
__device__ int2    g_cedge[NE];        // CSR: {src, weight-bits}

// ---------------- 1. fused: gather embeddings | count degrees -------------------
__global__ void k_gathercount(const int* __restrict__ ids, const float* __restrict__ emb,
                              const int* __restrict__ dst, const float* __restrict__ ew)
{
    int tid = threadIdx.x;
    if (blockIdx.x < GATHB) {
        int i = blockIdx.x * 256 + tid;
        if (i >= NN * DH) return;
        int node = i >> 6;
        g_h[i] = emb[(long)ids[node] * DH + (i & 63)];
    } else {
        for (int e = (blockIdx.x - GATHB) * 256 + tid; e < NE; e += CNTB * 256) {
            int d = dst[e];
            atomicAdd(&g_cnt[d], 1);
            atomicAdd(&g_degw[d], ew[e]);
        }
    }
}

// ---------------- 2. scan within 1024-blocks (+ reset g_cnt) --------------------
__global__ void k_scan1()
{
    __shared__ int s[SCAN_BLK];
    int tid = threadIdx.x;
    int i = blockIdx.x * SCAN_BLK + tid;
    int v = (i < NN) ? g_cnt[i] : 0;
    if (i < NN) g_cnt[i] = 0;                    // self-reset for next call
    s[tid] = v;
    __syncthreads();
    #pragma unroll
    for (int off = 1; off < SCAN_BLK; off <<= 1) {
        int t = (tid >= off) ? s[tid - off] : 0;
        __syncthreads();
        s[tid] += t;
        __syncthreads();
    }
    if (i < NN) g_rs[i] = s[tid] - v;            // exclusive within block
    if (tid == SCAN_BLK - 1) g_bsum[blockIdx.x] = s[tid];
}

// ---------------- 3. block-offset scan + finalize + dinv (+ reset degw) ---------
__global__ void k_scan23()
{
    __shared__ int bs[NSCAN];
    __shared__ int total_s;
    int tid = threadIdx.x;
    if (tid < NSCAN) bs[tid] = g_bsum[tid];
    __syncthreads();
    if (tid == 0) {
        int run = 0;
        for (int k = 0; k < NSCAN; k++) { int v = bs[k]; bs[k] = run; run += v; }
        total_s = run;
    }
    __syncthreads();
    int i = blockIdx.x * blockDim.x + tid;
    if (i == 0) g_rs[NN] = total_s;              // = NE
    if (i >= NN) return;
    int r = g_rs[i] + bs[i / SCAN_BLK];
    g_rs[i]  = r;
    g_cur[i] = r;
    float d = g_degw[i] + 1.0f;                  // + self-loop weight
    g_degw[i] = 0.0f;                            // self-reset for next call
    g_dinv[i] = rsqrtf(fmaxf(d, 1e-12f));        // d >= 1 always
}

// ---------------- 4. fused GEMM + (CSR fill | need-flag) blocks ------------------
// blocks [0, GEMMB): xs = (g_h @ W) * dinv[row] -> g_xh (fp16)
// blocks [GEMMB, ...): mode 1 = CSR fill (FILLB blocks); mode 2 = flag (FLAGB blocks)
__global__ void k_gemmfill(const float* __restrict__ W,
                           const int* __restrict__ src, const int* __restrict__ dst,
                           const float* __restrict__ ew,
                           const int* __restrict__ tsl, const int* __restrict__ trl,
                           const int* __restrict__ ptr, int mode)
{
    __shared__ float hs[64][65];
    __shared__ float ws[64][64];
    int tid = threadIdx.x;

    if (blockIdx.x >= GEMMB) {
        if (mode == 1) {
            // ---- CSR fill ----
            for (int e = (blockIdx.x - GEMMB) * 128 + tid; e < NE; e += FILLB * 128) {
                int d = dst[e];
                int pos = atomicAdd(&g_cur[d], 1);
                g_cedge[pos] = make_int2(src[e], __float_as_int(ew[e]));
            }
        } else {
            // ---- flag nodes needed by the MLP head (128 thr/blk, FLAGB*128 = BB) ----
            int row = (blockIdx.x - GEMMB) * 128 + tid;
            if (row < BB) {
                int off = ptr[row];
                g_need[tsl[row] + off] = 1;
                g_need[trl[row] + off] = 1;
            }
        }
        return;
    }

    // ---- GEMM tile ----
    int r0 = blockIdx.x * 64;
    for (int i = tid; i < 64 * 16; i += 128) {
        int r = i >> 4, c4 = (i & 15) * 4;
        float4 v = make_float4(0.f, 0.f, 0.f, 0.f);
        if (r0 + r < NN) v = ((const float4*)g_h)[(r0 + r) * 16 + (i & 15)];
        hs[r][c4] = v.x; hs[r][c4+1] = v.y; hs[r][c4+2] = v.z; hs[r][c4+3] = v.w;
        *((float4*)&ws[r][c4]) = ((const float4*)W)[i];
    }
    __syncthreads();

    int tx = tid & 15, ty = tid >> 4;
    int c0 = tx * 4;
    float4 acc[8];
    #pragma unroll
    for (int r = 0; r < 8; r++) acc[r] = make_float4(0.f, 0.f, 0.f, 0.f);

    #pragma unroll
    for (int k = 0; k < 64; k++) {
        float4 wv = *((const float4*)&ws[k][c0]);
        #pragma unroll
        for (int r = 0; r < 8; r++) {
            float a = hs[ty * 8 + r][k];
            acc[r].x += a * wv.x;
            acc[r].y += a * wv.y;
            acc[r].z += a * wv.z;
            acc[r].w += a * wv.w;
        }
    }
    #pragma unroll
    for (int r = 0; r < 8; r++) {
        int row = r0 + ty * 8 + r;
        if (row < NN) {
            float di = g_dinv[row];
            g_xh[row * 32 + tx * 2]     = __floats2half2_rn(acc[r].x * di, acc[r].y * di);
            g_xh[row * 32 + tx * 2 + 1] = __floats2half2_rn(acc[r].z * di, acc[r].w * di);
        }
    }
}

// ---------------- 5. gather aggregation + self-loop + bias + relu ----------------
// one warp per destination node; sparse=1: only flagged nodes (and reset flags)
__global__ void k_agg(const float* __restrict__ b, int sparse)
{
    int warp = blockIdx.x * (blockDim.x >> 5) + (threadIdx.x >> 5);
    if (warp >= NN) return;
    int lane = threadIdx.x & 31;

    if (sparse) {
        int need = g_need[warp];                 // all lanes read (broadcast)
        __syncwarp();                            // reads complete before reset
        if (!need) return;
        if (lane == 0) g_need[warp] = 0;         // self-reset for next call
    }

    int start = g_rs[warp];
    int end   = g_rs[warp + 1];
    float di  = g_dinv[warp];

    // self term: dinv^2 * x[d] = dinv * xs[d]
    float2 xs  = __half22float2(__ldg(&g_xh[warp * 32 + lane]));
    float2 acc = make_float2(xs.x * di, xs.y * di);

    int cnt = end - start;
    int n8  = start + (cnt & ~7);
    int j = start;
    for (; j < n8; j += 8) {
        int2 e[8];
        #pragma unroll
        for (int k = 0; k < 8; k++) e[k] = __ldg(&g_cedge[j + k]);
        float2 v[8];
        #pragma unroll
        for (int k = 0; k < 8; k++) v[k] = __half22float2(__ldg(&g_xh[e[k].x * 32 + lane]));
        #pragma unroll
        for (int k = 0; k < 8; k++) {
            float n = di * __int_as_float(e[k].y);
            acc.x += n * v[k].x;
            acc.y += n * v[k].y;
        }
    }
    for (; j < end; j++) {
        int2 e0 = __ldg(&g_cedge[j]);
        float2 v0 = __half22float2(__ldg(&g_xh[e0.x * 32 + lane]));
        float n = di * __int_as_float(e0.y);
        acc.x += n * v0.x;
        acc.y += n * v0.y;
    }

    float2 bb = ((const float2*)b)[lane];
    float2 o  = make_float2(fmaxf(acc.x + bb.x, 0.0f), fmaxf(acc.y + bb.y, 0.0f));
    ((float2*)g_h)[warp * 32 + lane] = o;
}

// ---------------- 6. fused MLP head ----------------------------------------------
__global__ void k_mlp(const int* __restrict__ tsl, const int* __restrict__ trl,
                      const int* __restrict__ ptr, const float* __restrict__ txf,
                      const float* __restrict__ Wtx, const float* __restrict__ btx,
                      const float* __restrict__ Wc1, const float* __restrict__ bc1,
                      const float* __restrict__ g1,  const float* __restrict__ beta1,
                      const float* __restrict__ Wc2, const float* __restrict__ bc2,
                      const float* __restrict__ g2,  const float* __restrict__ beta2,
                      const float* __restrict__ Wc3, const float* __restrict__ bc3,
                      float* __restrict__ out)
{
    __shared__ float Wc1s[160 * 64];
    for (int i = threadIdx.x; i < 160 * 64; i += blockDim.x) Wc1s[i] = Wc1[i];
    __syncthreads();

    const int lane = threadIdx.x & 31;
    const int row  = blockIdx.x * (blockDim.x >> 5) + (threadIdx.x >> 5);
    if (row >= BB) return;

    const float invs = rsqrtf(1.0f + BN_EPS);
    const unsigned FULL = 0xffffffffu;

    int off  = ptr[row];
    int sidx = tsl[row] + off;
    int ridx = trl[row] + off;

    float f = (lane < DTXF) ? txf[row * DTXF + lane] : 0.0f;
    float acct = __ldg(&btx[lane]);
    #pragma unroll
    for (int k = 0; k < DTXF; k++) {
        float tk = __shfl_sync(FULL, f, k);
        acct += tk * __ldg(&Wtx[k * DTX + lane]);
    }
    float txv = fmaxf(acct, 0.0f);

    float zr[5];
    zr[0] = g_h[sidx * DH + lane];
    zr[1] = g_h[sidx * DH + 32 + lane];
    zr[2] = g_h[ridx * DH + lane];
    zr[3] = g_h[ridx * DH + 32 + lane];
    zr[4] = txv;

    float2 a = make_float2(0.f, 0.f);
    #pragma unroll
    for (int k = 0; k < 160; k++) {
        float zk = __shfl_sync(FULL, zr[k >> 5], k & 31);
        float2 w = *(const float2*)&Wc1s[k * 64 + 2 * lane];
        a.x += zk * w.x;
        a.y += zk * w.y;
    }
    int c0 = 2 * lane, c1 = 2 * lane + 1;
    float z1x = fmaxf((a.x + __ldg(&bc1[c0])) * (__ldg(&g1[c0]) * invs) + __ldg(&beta1[c0]), 0.0f);
    float z1y = fmaxf((a.y + __ldg(&bc1[c1])) * (__ldg(&g1[c1]) * invs) + __ldg(&beta1[c1]), 0.0f);

    float acc2 = 0.0f;
    #pragma unroll
    for (int k = 0; k < DH; k++) {
        float zk = __shfl_sync(FULL, (k & 1) ? z1y : z1x, k >> 1);
        acc2 += zk * __ldg(&Wc2[k * 32 + lane]);
    }
    float z2v = fmaxf((acc2 + __ldg(&bc2[lane])) * (__ldg(&g2[lane]) * invs) + __ldg(&beta2[lane]), 0.0f);

    float p = z2v * __ldg(&Wc3[lane]);
    #pragma unroll
    for (int o = 16; o > 0; o >>= 1) p += __shfl_xor_sync(FULL, p, o);
    if (lane == 0) out[row] = p + __ldg(&bc3[0]);
}

// =============================== launch ========================================
extern "C" void kernel_launch(void* const* d_in, const int* in_sizes, int n_in,
                              void* d_out, int out_size)
{
    const int*   ids  = (const int*)  d_in[0];
    const int*   ei   = (const int*)  d_in[1];
    const float* ew   = (const float*)d_in[2];
    const int*   tsl  = (const int*)  d_in[3];
    const int*   trl  = (const int*)  d_in[4];
    const int*   ptr  = (const int*)  d_in[5];
    const float* txf  = (const float*)d_in[6];
    const float* emb  = (const float*)d_in[7];
    const float* W0   = (const float*)d_in[8];
    const float* b0   = (const float*)d_in[9];
    const float* W1   = (const float*)d_in[10];
    const float* b1   = (const float*)d_in[11];
    const float* Wtx  = (const float*)d_in[12];
    const float* btx  = (const float*)d_in[13];
    const float* Wc1  = (const float*)d_in[14];
    const float* bc1  = (const float*)d_in[15];
    const float* g1   = (const float*)d_in[16];
    const float* beta1= (const float*)d_in[17];
    const float* Wc2  = (const float*)d_in[18];
    const float* bc2  = (const float*)d_in[19];
    const float* g2   = (const float*)d_in[20];
    const float* beta2= (const float*)d_in[21];
    const float* Wc3  = (const float*)d_in[22];
    const float* bc3  = (const float*)d_in[23];
    float* out = (float*)d_out;

    const int* src = ei;
    const int* dst = ei + NE;

    // 1 fused embedding gather + degree count
    k_gathercount<<<GATHB + CNTB, 256>>>(ids, emb, dst, ew);
    // 2-3 scan + dinv
    k_scan1 <<<NSCAN, SCAN_BLK>>>();
    k_scan23<<<(NN + 255) / 256, 256>>>();

    // 4 GCN layer 0 GEMM + CSR fill (overlapped)
    k_gemmfill<<<GEMMB + FILLB, 128>>>(W0, src, dst, ew, tsl, trl, ptr, 1);
    // 5 layer 0 aggregation (all nodes)
    k_agg<<<(NN + 7) / 8, 256>>>(b0, 0);

    // 6 GCN layer 1 GEMM + need-flag (overlapped)
    k_gemmfill<<<GEMMB + FLAGB, 128>>>(W1, src, dst, ew, tsl, trl, ptr, 2);
    // 7 layer 1 aggregation (flagged nodes only)
    k_agg<<<(NN + 7) / 8, 256>>>(b1, 1);

    // 8 fused MLP head
    k_mlp<<<BB / 8, 256>>>(tsl, trl, ptr, txf,
                           Wtx, btx, Wc1, bc1, g1, beta1,
                           Wc2, bc2, g2, beta2, Wc3, bc3, out);
}

// round 7
// speedup vs baseline: 2.1031x; 1.1235x over previous
#include <cuda_runtime.h>
#include <cuda_fp16.h>
#include <math.h>

#define NN  100000      // nodes  (< 2^17)
#define NE  3200000     // edges
#define DH  64
#define DTXF 16
#define DTX  32
#define BB  16384
#define BN_EPS 1e-5f

#define SCAN_BLK 1024
#define NSCAN ((NN + SCAN_BLK - 1) / SCAN_BLK)   // 98

#define CNTB   2048                              // count blocks (grid-stride)
#define FLAGB  (BB / 256)                        // flag blocks: 64*256 = BB
#define GEMMB  ((NN + 127) / 128)                // 782 gemm blocks (128 rows each)
#define FILLB  2048                              // fill blocks (layer 0 launch)

#define W_FIX   1048576.0f                       // 2^20 weight fixed-point
#define MASK44  ((1ULL << 44) - 1)
#define WQ_SCALE 32767.0f                        // 15-bit edge weight quant

// ---------------- scratch (device globals; self-resetting or overwritten) -------
__device__ float              g_h   [NN * DH];   // node features (layer outputs)
__device__ __half2            g_xh  [NN * 32];   // fp16 rows of (h@W)*dinv[row]
__device__ unsigned long long g_pack[NN];        // count<<44 | degw_fix ; reset in scan23
__device__ float              g_dinv[NN];
__device__ int                g_rs  [NN + 1];    // CSR row starts (by dst)
__device__ int                g_cur [NN];        // fill cursors
__device__ int                g_bsum[NSCAN];
__device__ int                g_need[NN];        // reset in sparse k_agg
__device__ unsigned           g_cedge[NE];       // CSR: src<<15 | wq(15 bits)

// ---------------- 1. fused: packed degree count | MLP need-flags ----------------
__global__ void k_countflag(const int* __restrict__ dst, const float* __restrict__ ew,
                            const int* __restrict__ tsl, const int* __restrict__ trl,
                            const int* __restrict__ ptr)
{
    int tid = threadIdx.x;
    if (blockIdx.x < CNTB) {
        for (int e = blockIdx.x * 256 + tid; e < NE; e += CNTB * 256) {
            unsigned long long v = (1ULL << 44)
                | (unsigned long long)__float2uint_rn(ew[e] * W_FIX);
            atomicAdd(&g_pack[dst[e]], v);
        }
    } else {
        int row = (blockIdx.x - CNTB) * 256 + tid;
        if (row < BB) {
            int off = ptr[row];
            g_need[tsl[row] + off] = 1;
            g_need[trl[row] + off] = 1;
        }
    }
}

// ---------------- 2. scan within 1024-blocks ------------------------------------
__global__ void k_scan1()
{
    __shared__ int s[SCAN_BLK];
    int tid = threadIdx.x;
    int i = blockIdx.x * SCAN_BLK + tid;
    int v = (i < NN) ? (int)(g_pack[i] >> 44) : 0;
    s[tid] = v;
    __syncthreads();
    #pragma unroll
    for (int off = 1; off < SCAN_BLK; off <<= 1) {
        int t = (tid >= off) ? s[tid - off] : 0;
        __syncthreads();
        s[tid] += t;
        __syncthreads();
    }
    if (i < NN) g_rs[i] = s[tid] - v;            // exclusive within block
    if (tid == SCAN_BLK - 1) g_bsum[blockIdx.x] = s[tid];
}

// ---------------- 3. block-offset scan + finalize + dinv (+ reset pack) ---------
__global__ void k_scan23()
{
    __shared__ int bs[NSCAN];
    __shared__ int total_s;
    int tid = threadIdx.x;
    if (tid < NSCAN) bs[tid] = g_bsum[tid];
    __syncthreads();
    if (tid == 0) {
        int run = 0;
        for (int k = 0; k < NSCAN; k++) { int v = bs[k]; bs[k] = run; run += v; }
        total_s = run;
    }
    __syncthreads();
    int i = blockIdx.x * blockDim.x + tid;
    if (i == 0) g_rs[NN] = total_s;              // = NE
    if (i >= NN) return;
    int r = g_rs[i] + bs[i / SCAN_BLK];
    g_rs[i]  = r;
    g_cur[i] = r;
    unsigned long long p = g_pack[i];
    g_pack[i] = 0ULL;                            // self-reset for next call
    float d = (float)(p & MASK44) * (1.0f / W_FIX) + 1.0f;  // + self-loop
    g_dinv[i] = rsqrtf(d);                        // d >= 1
}

// ---------------- 4. fused GEMM (+ CSR fill blocks, layer 0) --------------------
// fill=1: blocks [0, FILLB) = CSR fill; [FILLB, FILLB+GEMMB) = gemm
// fill=0: all blocks gemm
// ids != null: A rows gathered from emb[ids[row]] (layer 0); else from g_h.
__global__ void __launch_bounds__(256)
k_gemmfill(const float* __restrict__ W,
           const int* __restrict__ ids, const float* __restrict__ emb,
           const int* __restrict__ src, const int* __restrict__ dst,
           const float* __restrict__ ew, int fill)
{
    __shared__ float hs[128][65];   // 33.3 KB
    __shared__ float ws[64][64];    // 16 KB
    int tid = threadIdx.x;
    int bx  = blockIdx.x;

    if (fill) {
        if (bx < FILLB) {
            // ---- CSR fill: packed 4B entries ----
            for (int e = bx * 256 + tid; e < NE; e += FILLB * 256) {
                int d = dst[e];
                unsigned wq = __float2uint_rn(ew[e] * WQ_SCALE);
                int pos = atomicAdd(&g_cur[d], 1);
                g_cedge[pos] = ((unsigned)src[e] << 15) | wq;
            }
            return;
        }
        bx -= FILLB;
    }

    // ---- GEMM tile: 128 rows ----
    int r0 = bx * 128;
    for (int i = tid; i < 128 * 16; i += 256) {
        int r = i >> 4, c = i & 15, c4 = c * 4;
        float4 v = make_float4(0.f, 0.f, 0.f, 0.f);
        int row = r0 + r;
        if (row < NN) {
            if (ids) v = ((const float4*)(emb + (long)ids[row] * DH))[c];
            else     v = ((const float4*)g_h)[row * 16 + c];
        }
        hs[r][c4] = v.x; hs[r][c4+1] = v.y; hs[r][c4+2] = v.z; hs[r][c4+3] = v.w;
    }
    for (int i = tid; i < 64 * 16; i += 256) {
        int r = i >> 4, c4 = (i & 15) * 4;
        *((float4*)&ws[r][c4]) = ((const float4*)W)[i];
    }
    __syncthreads();

    int tx = tid & 15, ty = tid >> 4;            // 16 x 16 threads
    int c0 = tx * 4;
    float4 acc[8];
    #pragma unroll
    for (int r = 0; r < 8; r++) acc[r] = make_float4(0.f, 0.f, 0.f, 0.f);

    #pragma unroll
    for (int k = 0; k < 64; k++) {
        float4 wv = *((const float4*)&ws[k][c0]);
        #pragma unroll
        for (int r = 0; r < 8; r++) {
            float a = hs[ty * 8 + r][k];
            acc[r].x += a * wv.x;
            acc[r].y += a * wv.y;
            acc[r].z += a * wv.z;
            acc[r].w += a * wv.w;
        }
    }
    #pragma unroll
    for (int r = 0; r < 8; r++) {
        int row = r0 + ty * 8 + r;
        if (row < NN) {
            float di = g_dinv[row];
            g_xh[row * 32 + tx * 2]     = __floats2half2_rn(acc[r].x * di, acc[r].y * di);
            g_xh[row * 32 + tx * 2 + 1] = __floats2half2_rn(acc[r].z * di, acc[r].w * di);
        }
    }
}

// ---------------- 5. gather aggregation + self-loop + bias + relu ----------------
// one warp per destination node; sparse=1: only flagged nodes (and reset flags)
__global__ void k_agg(const float* __restrict__ b, int sparse)
{
    int warp = blockIdx.x * (blockDim.x >> 5) + (threadIdx.x >> 5);
    if (warp >= NN) return;
    int lane = threadIdx.x & 31;

    if (sparse) {
        int need = g_need[warp];                 // all lanes read (broadcast)
        __syncwarp();
        if (!need) return;
        if (lane == 0) g_need[warp] = 0;         // self-reset for next call
    }

    int start = g_rs[warp];
    int end   = g_rs[warp + 1];
    float di  = g_dinv[warp];

    // self term: dinv^2 * x[d] = dinv * xs[d]
    float2 xs  = __half22float2(__ldg(&g_xh[warp * 32 + lane]));
    float2 acc = make_float2(xs.x * di, xs.y * di);

    const float wdq = 1.0f / WQ_SCALE;
    int cnt = end - start;
    int n8  = start + (cnt & ~7);
    int j = start;
    for (; j < n8; j += 8) {
        unsigned e[8];
        #pragma unroll
        for (int k = 0; k < 8; k++) e[k] = __ldg(&g_cedge[j + k]);
        float2 v[8];
        #pragma unroll
        for (int k = 0; k < 8; k++)
            v[k] = __half22float2(__ldg(&g_xh[(e[k] >> 15) * 32 + lane]));
        #pragma unroll
        for (int k = 0; k < 8; k++) {
            float n = di * (float)(e[k] & 0x7FFFu) * wdq;
            acc.x += n * v[k].x;
            acc.y += n * v[k].y;
        }
    }
    for (; j < end; j++) {
        unsigned e0 = __ldg(&g_cedge[j]);
        float2 v0 = __half22float2(__ldg(&g_xh[(e0 >> 15) * 32 + lane]));
        float n = di * (float)(e0 & 0x7FFFu) * wdq;
        acc.x += n * v0.x;
        acc.y += n * v0.y;
    }

    float2 bb = ((const float2*)b)[lane];
    float2 o  = make_float2(fmaxf(acc.x + bb.x, 0.0f), fmaxf(acc.y + bb.y, 0.0f));
    ((float2*)g_h)[warp * 32 + lane] = o;
}

// ---------------- 6. fused MLP head ----------------------------------------------
__global__ void k_mlp(const int* __restrict__ tsl, const int* __restrict__ trl,
                      const int* __restrict__ ptr, const float* __restrict__ txf,
                      const float* __restrict__ Wtx, const float* __restrict__ btx,
                      const float* __restrict__ Wc1, const float* __restrict__ bc1,
                      const float* __restrict__ g1,  const float* __restrict__ beta1,
                      const float* __restrict__ Wc2, const float* __restrict__ bc2,
                      const float* __restrict__ g2,  const float* __restrict__ beta2,
                      const float* __restrict__ Wc3, const float* __restrict__ bc3,
                      float* __restrict__ out)
{
    __shared__ float Wc1s[160 * 64];
    for (int i = threadIdx.x; i < 160 * 64; i += blockDim.x) Wc1s[i] = Wc1[i];
    __syncthreads();

    const int lane = threadIdx.x & 31;
    const int row  = blockIdx.x * (blockDim.x >> 5) + (threadIdx.x >> 5);
    if (row >= BB) return;

    const float invs = rsqrtf(1.0f + BN_EPS);
    const unsigned FULL = 0xffffffffu;

    int off  = ptr[row];
    int sidx = tsl[row] + off;
    int ridx = trl[row] + off;

    float f = (lane < DTXF) ? txf[row * DTXF + lane] : 0.0f;
    float acct = __ldg(&btx[lane]);
    #pragma unroll
    for (int k = 0; k < DTXF; k++) {
        float tk = __shfl_sync(FULL, f, k);
        acct += tk * __ldg(&Wtx[k * DTX + lane]);
    }
    float txv = fmaxf(acct, 0.0f);

    float zr[5];
    zr[0] = g_h[sidx * DH + lane];
    zr[1] = g_h[sidx * DH + 32 + lane];
    zr[2] = g_h[ridx * DH + lane];
    zr[3] = g_h[ridx * DH + 32 + lane];
    zr[4] = txv;

    float2 a = make_float2(0.f, 0.f);
    #pragma unroll
    for (int k = 0; k < 160; k++) {
        float zk = __shfl_sync(FULL, zr[k >> 5], k & 31);
        float2 w = *(const float2*)&Wc1s[k * 64 + 2 * lane];
        a.x += zk * w.x;
        a.y += zk * w.y;
    }
    int c0 = 2 * lane, c1 = 2 * lane + 1;
    float z1x = fmaxf((a.x + __ldg(&bc1[c0])) * (__ldg(&g1[c0]) * invs) + __ldg(&beta1[c0]), 0.0f);
    float z1y = fmaxf((a.y + __ldg(&bc1[c1])) * (__ldg(&g1[c1]) * invs) + __ldg(&beta1[c1]), 0.0f);

    float acc2 = 0.0f;
    #pragma unroll
    for (int k = 0; k < DH; k++) {
        float zk = __shfl_sync(FULL, (k & 1) ? z1y : z1x, k >> 1);
        acc2 += zk * __ldg(&Wc2[k * 32 + lane]);
    }
    float z2v = fmaxf((acc2 + __ldg(&bc2[lane])) * (__ldg(&g2[lane]) * invs) + __ldg(&beta2[lane]), 0.0f);

    float p = z2v * __ldg(&Wc3[lane]);
    #pragma unroll
    for (int o = 16; o > 0; o >>= 1) p += __shfl_xor_sync(FULL, p, o);
    if (lane == 0) out[row] = p + __ldg(&bc3[0]);
}

// =============================== launch ========================================
extern "C" void kernel_launch(void* const* d_in, const int* in_sizes, int n_in,
                              void* d_out, int out_size)
{
    const int*   ids  = (const int*)  d_in[0];
    const int*   ei   = (const int*)  d_in[1];
    const float* ew   = (const float*)d_in[2];
    const int*   tsl  = (const int*)  d_in[3];
    const int*   trl  = (const int*)  d_in[4];
    const int*   ptr  = (const int*)  d_in[5];
    const float* txf  = (const float*)d_in[6];
    const float* emb  = (const float*)d_in[7];
    const float* W0   = (const float*)d_in[8];
    const float* b0   = (const float*)d_in[9];
    const float* W1   = (const float*)d_in[10];
    const float* b1   = (const float*)d_in[11];
    const float* Wtx  = (const float*)d_in[12];
    const float* btx  = (const float*)d_in[13];
    const float* Wc1  = (const float*)d_in[14];
    const float* bc1  = (const float*)d_in[15];
    const float* g1   = (const float*)d_in[16];
    const float* beta1= (const float*)d_in[17];
    const float* Wc2  = (const float*)d_in[18];
    const float* bc2  = (const float*)d_in[19];
    const float* g2   = (const float*)d_in[20];
    const float* beta2= (const float*)d_in[21];
    const float* Wc3  = (const float*)d_in[22];
    const float* bc3  = (const float*)d_in[23];
    float* out = (float*)d_out;

    const int* src = ei;
    const int* dst = ei + NE;

    // 1 packed degree count + MLP need-flags
    k_countflag<<<CNTB + FLAGB, 256>>>(dst, ew, tsl, trl, ptr);
    // 2-3 scan + dinv
    k_scan1 <<<NSCAN, SCAN_BLK>>>();
    k_scan23<<<(NN + 255) / 256, 256>>>();

    // 4 GCN layer 0: CSR fill (first) + GEMM with fused emb gather
    k_gemmfill<<<FILLB + GEMMB, 256>>>(W0, ids, emb, src, dst, ew, 1);
    // 5 layer 0 aggregation (all nodes)
    k_agg<<<(NN + 7) / 8, 256>>>(b0, 0);

    // 6 GCN layer 1 GEMM (reads g_h)
    k_gemmfill<<<GEMMB, 256>>>(W1, (const int*)0, emb, src, dst, ew, 0);
    // 7 layer 1 aggregation (flagged nodes only)
    k_agg<<<(NN + 7) / 8, 256>>>(b1, 1);

    // 8 fused MLP head
    k_mlp<<<BB / 8, 256>>>(tsl, trl, ptr, txf,
                           Wtx, btx, Wc1, bc1, g1, beta1,
                           Wc2, bc2, g2, beta2, Wc3, bc3, out);
}